// round 15
// baseline (speedup 1.0000x reference)
#include <cuda_runtime.h>
#include <math.h>

#define BB 256
#define NN 2048
#define RR 64
#define DD 64
#define TT 8
#define HH 128
#define KD 128

#define GRID    444           // 3 CTAs on every SM (148 x 3), all co-resident
#define NTHR    256
#define MCH     32            // nodes per chunk
#define MS      (MCH + 4)     // smem row stride
#define LMAX    256
#define NGRP    (LMAX * TT)   // bucket key = t*LMAX + L

// packed f32x2 ops (sm_103a double-rate fp32 path; ptxas never auto-emits)
#define FMA_F32X2(d, a, b, c) \
    asm("fma.rn.f32x2 %0, %1, %2, %3;" : "=l"(d) : "l"(a), "l"(b), "l"(c))
#define PACK_F32X2(out, lo, hi) \
    asm("mov.b64 %0, {%1, %2};" : "=l"(out) : "f"(lo), "f"(hi))
#define UNPACK_F32X2(lo, hi, in) \
    asm("mov.b64 {%0, %1}, %2;" : "=f"(lo), "=f"(hi) : "l"(in))

// ---------------- global scratch (static: no allocation) ----------------
__device__ unsigned           g_arrive;
__device__ volatile unsigned  g_release;
__device__ int                g_cnt[NGRP];
__device__ int                g_cur[NGRP];             // scatter cursors
__device__ int                g_off[NGRP + 1];         // node offsets, type-major
__device__ int                g_ccum[LMAX + 1];        // LEVEL-major global chunk prefix
__device__ int                g_qcur;                  // single global chunk cursor
__device__ int                g_maxl;
__device__ unsigned long long g_items[BB * (NN - RR)]; // (b<<33)|(n<<22)|(p0<<11)|p1
__device__ unsigned           g_flag[BB * NN];         // node-done flags

__global__ void reset_kernel()
{
    int gt = blockIdx.x * NTHR + threadIdx.x;
    for (int i = gt; i < BB * NN; i += GRID * NTHR) g_flag[i] = 0u;
    for (int i = gt; i < NGRP;   i += GRID * NTHR) g_cnt[i] = 0;
    if (gt == 0) { g_arrive = 0; g_release = 0; g_maxl = 0; g_qcur = 0; }
}

__device__ __forceinline__ void grid_barrier(int k)
{
    __syncthreads();
    if (threadIdx.x == 0) {
        __threadfence();   // release side
        unsigned old = atomicAdd(&g_arrive, 1u);
        if (old == (unsigned)(k * GRID - 1)) {
            g_release = (unsigned)k;
        } else {
            while (g_release < (unsigned)k) { }
        }
        __threadfence();   // acquire side
    }
    __syncthreads();
}

// STRONG scoped flag ops — the canonical PTX release/acquire message pair.
__device__ __forceinline__ unsigned ld_acq_u32(const unsigned* p)
{
    unsigned v;
    asm volatile("ld.acquire.gpu.global.u32 %0, [%1];"
                 : "=r"(v) : "l"(p) : "memory");
    return v;
}
__device__ __forceinline__ void st_rel_u32(unsigned* p, unsigned v)
{
    asm volatile("st.release.gpu.global.u32 [%0], %1;"
                 :: "l"(p), "r"(v) : "memory");
}

__global__ __launch_bounds__(NTHR, 3)
void dag_global_kernel(const float* __restrict__ roots,
                       const float* __restrict__ W1,
                       const float* __restrict__ b1,
                       const float* __restrict__ W2,
                       const float* __restrict__ b2,
                       const int*   __restrict__ g_idx,
                       const int*   __restrict__ g_typ,
                       float*       __restrict__ buf)
{
    const int b    = blockIdx.x;
    const int tid  = threadIdx.x;
    const int lane = tid & 31;
    const int wid  = tid >> 5;

    __shared__ __align__(16) float s_xs[KD * MS];
    __shared__ __align__(16) float s_hs[HH * MS];
    __shared__ unsigned long long s_it[MCH];     // chunk items (smem copy)
    __shared__ int s_ccum[LMAX + 1];
    __shared__ int s_k, s_t, s_goff, s_Mc;

    unsigned short* s_lvl  = (unsigned short*)s_xs;   // prep aliases
    unsigned short* s_pidx = (unsigned short*)s_hs;

    // ---------------- prep (graphs 0..BB-1 handled by CTAs 0..BB-1) ----------
    if (b < BB) {
        const int* idxb = g_idx + (size_t)b * (NN * 2);
        const float* rs = roots + (size_t)b * (RR * DD);
        float*       bb = buf   + (size_t)b * (NN * DD);
        for (int i = tid; i < RR * DD; i += NTHR) bb[i] = rs[i];
        for (int k = tid; k < NN * 2; k += NTHR)
            s_pidx[k] = (unsigned short)idxb[k];
        for (int n = tid; n < RR; n += NTHR)
            g_flag[b * NN + n] = 1u;
        __syncthreads();

        if (tid == 0) {
            for (int n = 0; n < RR; ++n) s_lvl[n] = 0;
            int mx = 0;
            for (int n = RR; n < NN; ++n) {
                int l0 = s_lvl[s_pidx[n * 2 + 0]];
                int l1 = s_lvl[s_pidx[n * 2 + 1]];
                int l  = 1 + (l0 > l1 ? l0 : l1);
                s_lvl[n] = (unsigned short)l;
                if (l > mx) mx = l;
            }
            atomicMax(&g_maxl, mx);
        }
        __syncthreads();

        const int* typb = g_typ + (size_t)b * NN;
        for (int n = RR + tid; n < NN; n += NTHR)
            atomicAdd(&g_cnt[typb[n] * LMAX + (int)s_lvl[n]], 1);
    }

    grid_barrier(1);

    // CTA0: per-type node-offset prefix sums + level-major chunk prefix
    if (b == 0) {
        __shared__ int s_ttot[TT];
        if (tid < TT) {
            int tot = 0;
            for (int L = 0; L < LMAX; ++L) tot += g_cnt[tid * LMAX + L];
            s_ttot[tid] = tot;
        }
        __syncthreads();
        if (tid < TT) {
            int base = 0;
            for (int t = 0; t < tid; ++t) base += s_ttot[t];
            int acc = base;
            for (int L = 0; L < LMAX; ++L) {
                g_off[tid * LMAX + L] = acc;
                g_cur[tid * LMAX + L] = acc;
                acc += g_cnt[tid * LMAX + L];
            }
            if (tid == TT - 1) g_off[NGRP] = acc;
        }
        if (tid == NTHR - 1) {           // level-major chunk prefix (needs only g_cnt)
            int acc = 0;
            g_ccum[0] = 0;
            for (int L = 1; L <= LMAX; ++L) {
                for (int t = 0; t < TT; ++t)
                    acc += (g_cnt[t * LMAX + (L - 1) + 1 - 1 + 0] * 0)  // keep indices obvious
                         + (g_cnt[t * LMAX + L] + MCH - 1) / MCH;
                g_ccum[L] = acc;
            }
        }
    }
    grid_barrier(2);

    // scatter items (64-bit packed with parent indices)
    if (b < BB) {
        const int* typb = g_typ + (size_t)b * NN;
        for (int n = RR + tid; n < NN; n += NTHR) {
            int key = typb[n] * LMAX + (int)s_lvl[n];
            int pos = atomicAdd(&g_cur[key], 1);
            unsigned long long p0 = s_pidx[n * 2 + 0];
            unsigned long long p1 = s_pidx[n * 2 + 1];
            g_items[pos] = ((unsigned long long)b << 33)
                         | ((unsigned long long)n << 22) | (p0 << 11) | p1;
        }
    }
    grid_barrier(3);

    // ---------------- dataflow main loop (single global queue) ----------------
    const int Lmx = *(volatile int*)&g_maxl;

    for (int i = tid; i <= LMAX; i += NTHR) s_ccum[i] = g_ccum[i];
    __syncthreads();
    const int total = s_ccum[Lmx];

    const int j128 = tid & 127, mh = tid >> 7;

    while (true) {
        // tid0 claims a chunk and resolves (level, type, node range)
        if (tid == 0) {
            int k = atomicAdd(&g_qcur, 1);
            s_k = k;
            if (k < total) {
                int loL = 1, hiL = Lmx;
                while (loL < hiL) { int mid = (loL + hiL) >> 1;
                                    if (s_ccum[mid] > k) hiL = mid; else loL = mid + 1; }
                const int L = loL;
                int r = k - s_ccum[L - 1];
                int t = 0, goff = 0, rem = 0;
                for (t = 0; t < TT; ++t) {
                    int o0 = g_off[t * LMAX + L];
                    int o1 = g_off[t * LMAX + L + 1];
                    int c  = o1 - o0;
                    int nc = (c + MCH - 1) / MCH;
                    if (r < nc) { goff = o0 + r * MCH; rem = c - r * MCH; break; }
                    r -= nc;
                }
                s_t = t; s_goff = goff; s_Mc = min(MCH, rem);
            }
        }
        __syncthreads();
        if (s_k >= total) break;
        const int t    = s_t;
        const int goff = s_goff;
        const int Mc   = s_Mc;

        const float* w1t = W1 + (size_t)t * (KD * HH);
        const float* w2t = W2 + (size_t)t * (HH * DD);

        // stage items into smem (consumed after the gather sync)
        if (tid < Mc) s_it[tid] = g_items[goff + tid];

        // ---- two-phase poll: batch acquire loads (MLP=8), spin on rare misses ----
        unsigned long long itv[4];
        unsigned miss = 0u;
        #pragma unroll
        for (int r = 0; r < 4; ++r) {
            int m = wid + r * 8;
            itv[r] = 0;
            if (m < Mc) {
                itv[r] = g_items[goff + m];
                unsigned gb = (unsigned)(itv[r] >> 33);
                unsigned p0 = (unsigned)(itv[r] >> 11) & 2047u;
                unsigned p1 = (unsigned)itv[r] & 2047u;
                if (ld_acq_u32(&g_flag[gb * NN + p0]) == 0u) miss |= 1u << (2 * r);
                if (ld_acq_u32(&g_flag[gb * NN + p1]) == 0u) miss |= 1u << (2 * r + 1);
            }
        }
        if (miss) {
            #pragma unroll
            for (int r = 0; r < 4; ++r) {
                unsigned gb = (unsigned)(itv[r] >> 33);
                unsigned p0 = (unsigned)(itv[r] >> 11) & 2047u;
                unsigned p1 = (unsigned)itv[r] & 2047u;
                if (miss & (1u << (2 * r)))
                    while (ld_acq_u32(&g_flag[gb * NN + p0]) == 0u) { }
                if (miss & (1u << (2 * r + 1)))
                    while (ld_acq_u32(&g_flag[gb * NN + p1]) == 0u) { }
            }
        }

        // ---- gather (ordered after acquire loads in program order) ----
        #pragma unroll
        for (int r = 0; r < 4; ++r) {
            int m = wid + r * 8;
            if (m < Mc) {
                unsigned gb = (unsigned)(itv[r] >> 33);
                unsigned p0 = (unsigned)(itv[r] >> 11) & 2047u;
                unsigned p1 = (unsigned)itv[r] & 2047u;
                const float* r0 = buf + ((size_t)gb * NN + p0) * DD;
                const float* r1 = buf + ((size_t)gb * NN + p1) * DD;
                s_xs[(lane      ) * MS + m] = __ldcg(r0 + lane);
                s_xs[(lane + 32 ) * MS + m] = __ldcg(r0 + lane + 32);
                s_xs[(lane + 64 ) * MS + m] = __ldcg(r1 + lane);
                s_xs[(lane + 96 ) * MS + m] = __ldcg(r1 + lane + 32);
            }
        }
        __syncthreads();

        // ---- GEMM1 + bias + GELU: pipelined weights + packed f32x2 FMA ----
        {
            const float* wp = w1t + j128;
            const float* xp = s_xs + mh * 16;
            unsigned long long acc[8];
            #pragma unroll
            for (int q = 0; q < 8; ++q) acc[q] = 0ull;   // (0.0f, 0.0f)
            float wc0 = __ldg(wp + 0 * HH);
            float wc1 = __ldg(wp + 1 * HH);
            float wc2 = __ldg(wp + 2 * HH);
            float wc3 = __ldg(wp + 3 * HH);
            #pragma unroll 1
            for (int i = 0; i < KD; i += 4) {
                const int ip = (i + 4) & (KD - 1);   // wrap: harmless reload of block 0
                float wn0 = __ldg(wp + (ip + 0) * HH);
                float wn1 = __ldg(wp + (ip + 1) * HH);
                float wn2 = __ldg(wp + (ip + 2) * HH);
                float wn3 = __ldg(wp + (ip + 3) * HH);
                #pragma unroll
                for (int u = 0; u < 4; ++u) {
                    float wv = (u == 0) ? wc0 : (u == 1) ? wc1 : (u == 2) ? wc2 : wc3;
                    unsigned long long wv2;
                    PACK_F32X2(wv2, wv, wv);
                    const float* xr = xp + (i + u) * MS;
                    ulonglong2 x01 = *(const ulonglong2*)(xr     );
                    ulonglong2 x23 = *(const ulonglong2*)(xr + 4 );
                    ulonglong2 x45 = *(const ulonglong2*)(xr + 8 );
                    ulonglong2 x67 = *(const ulonglong2*)(xr + 12);
                    FMA_F32X2(acc[0], x01.x, wv2, acc[0]);
                    FMA_F32X2(acc[1], x01.y, wv2, acc[1]);
                    FMA_F32X2(acc[2], x23.x, wv2, acc[2]);
                    FMA_F32X2(acc[3], x23.y, wv2, acc[3]);
                    FMA_F32X2(acc[4], x45.x, wv2, acc[4]);
                    FMA_F32X2(acc[5], x45.y, wv2, acc[5]);
                    FMA_F32X2(acc[6], x67.x, wv2, acc[6]);
                    FMA_F32X2(acc[7], x67.y, wv2, acc[7]);
                }
                wc0 = wn0; wc1 = wn1; wc2 = wn2; wc3 = wn3;
            }
            float a[16];
            #pragma unroll
            for (int q = 0; q < 8; ++q)
                UNPACK_F32X2(a[2 * q], a[2 * q + 1], acc[q]);
            const float bv1 = __ldg(b1 + t * HH + j128);
            #pragma unroll
            for (int q = 0; q < 16; ++q) {
                float v = a[q] + bv1;
                a[q] = 0.5f * v * (1.0f + erff(v * 0.70710678118654752440f));
            }
            float* hp = s_hs + j128 * MS + mh * 16;
            *(float4*)(hp     ) = make_float4(a[0],  a[1],  a[2],  a[3]);
            *(float4*)(hp + 4 ) = make_float4(a[4],  a[5],  a[6],  a[7]);
            *(float4*)(hp + 8 ) = make_float4(a[8],  a[9],  a[10], a[11]);
            *(float4*)(hp + 12) = make_float4(a[12], a[13], a[14], a[15]);
        }
        __syncthreads();

        // ---- GEMM2 + bias + store: 128 threads x 16 m (halved mem pressure) ----
        if (tid < 128) {
            const int d   = tid & 63;
            const int mh2 = tid >> 6;          // 0..1
            const float* wp = w2t + d;
            const float* hp = s_hs + mh2 * 16;
            unsigned long long acc[8];
            #pragma unroll
            for (int q = 0; q < 8; ++q) acc[q] = 0ull;
            float wc0 = __ldg(wp + 0 * DD);
            float wc1 = __ldg(wp + 1 * DD);
            float wc2 = __ldg(wp + 2 * DD);
            float wc3 = __ldg(wp + 3 * DD);
            #pragma unroll 1
            for (int j = 0; j < HH; j += 4) {
                const int jp = (j + 4) & (HH - 1);
                float wn0 = __ldg(wp + (jp + 0) * DD);
                float wn1 = __ldg(wp + (jp + 1) * DD);
                float wn2 = __ldg(wp + (jp + 2) * DD);
                float wn3 = __ldg(wp + (jp + 3) * DD);
                #pragma unroll
                for (int u = 0; u < 4; ++u) {
                    float wv = (u == 0) ? wc0 : (u == 1) ? wc1 : (u == 2) ? wc2 : wc3;
                    unsigned long long wv2;
                    PACK_F32X2(wv2, wv, wv);
                    const float* hr = hp + (j + u) * MS;
                    ulonglong2 h01 = *(const ulonglong2*)(hr     );
                    ulonglong2 h23 = *(const ulonglong2*)(hr + 4 );
                    ulonglong2 h45 = *(const ulonglong2*)(hr + 8 );
                    ulonglong2 h67 = *(const ulonglong2*)(hr + 12);
                    FMA_F32X2(acc[0], h01.x, wv2, acc[0]);
                    FMA_F32X2(acc[1], h01.y, wv2, acc[1]);
                    FMA_F32X2(acc[2], h23.x, wv2, acc[2]);
                    FMA_F32X2(acc[3], h23.y, wv2, acc[3]);
                    FMA_F32X2(acc[4], h45.x, wv2, acc[4]);
                    FMA_F32X2(acc[5], h45.y, wv2, acc[5]);
                    FMA_F32X2(acc[6], h67.x, wv2, acc[6]);
                    FMA_F32X2(acc[7], h67.y, wv2, acc[7]);
                }
                wc0 = wn0; wc1 = wn1; wc2 = wn2; wc3 = wn3;
            }
            float o[16];
            #pragma unroll
            for (int q = 0; q < 8; ++q)
                UNPACK_F32X2(o[2 * q], o[2 * q + 1], acc[q]);
            const float bv2 = __ldg(b2 + t * DD + d);
            #pragma unroll
            for (int q = 0; q < 16; ++q) {
                int m = mh2 * 16 + q;
                if (m < Mc) {
                    unsigned long long it = s_it[m];             // broadcast LDS
                    unsigned gb = (unsigned)(it >> 33);
                    unsigned gn = (unsigned)(it >> 22) & 2047u;
                    buf[((size_t)gb * NN + gn) * DD + d] = o[q] + bv2;
                }
            }
        }

        // ---- publish: bar (intra-CTA HB) -> release-store (gpu-scope) ----
        __syncthreads();
        if (tid < Mc) {
            unsigned long long it = s_it[tid];
            unsigned gb = (unsigned)(it >> 33);
            unsigned gn = (unsigned)(it >> 22) & 2047u;
            st_rel_u32(&g_flag[gb * NN + gn], 1u);
        }
    }
}

extern "C" void kernel_launch(void* const* d_in, const int* in_sizes, int n_in,
                              void* d_out, int out_size)
{
    const float* roots = (const float*)d_in[0];
    const float* W1    = (const float*)d_in[1];
    const float* b1    = (const float*)d_in[2];
    const float* W2    = (const float*)d_in[3];
    const float* b2    = (const float*)d_in[4];
    const int*   idx   = (const int*)  d_in[5];
    const int*   typ   = (const int*)  d_in[6];
    float*       out   = (float*)d_out;

    reset_kernel<<<GRID, NTHR>>>();
    dag_global_kernel<<<GRID, NTHR>>>(roots, W1, b1, W2, b2, idx, typ, out);
}

// round 16
// speedup vs baseline: 1.1397x; 1.1397x over previous
#include <cuda_runtime.h>
#include <math.h>

#define BB 256
#define NN 2048
#define RR 64
#define DD 64
#define TT 8
#define HH 128
#define KD 128

#define GRID    444           // 3 CTAs on every SM (148 x 3), all co-resident
#define NTHR    256
#define MCH     32            // nodes per chunk
#define MS      (MCH + 4)     // smem row stride
#define LMAX    256
#define NGRP    (LMAX * TT)   // bucket key = t*LMAX + L

// packed f32x2 ops (sm_103a double-rate fp32 path; ptxas never auto-emits)
#define FMA_F32X2(d, a, b, c) \
    asm("fma.rn.f32x2 %0, %1, %2, %3;" : "=l"(d) : "l"(a), "l"(b), "l"(c))
#define PACK_F32X2(out, lo, hi) \
    asm("mov.b64 %0, {%1, %2};" : "=l"(out) : "f"(lo), "f"(hi))
#define UNPACK_F32X2(lo, hi, in) \
    asm("mov.b64 {%0, %1}, %2;" : "=f"(lo), "=f"(hi) : "l"(in))

// ---------------- global scratch (static: no allocation) ----------------
__device__ unsigned           g_arrive;
__device__ volatile unsigned  g_release;
__device__ int                g_cnt[NGRP];
__device__ int                g_cur[NGRP];             // scatter cursors
__device__ int                g_off[NGRP + 1];
__device__ int                g_ccum[TT * (LMAX + 1)]; // per-type chunk prefix over levels
__device__ int                g_tcur[TT];              // per-type team chunk cursor
__device__ int                g_maxl;
__device__ unsigned long long g_items[BB * (NN - RR)]; // (b<<33)|(n<<22)|(p0<<11)|p1
__device__ unsigned           g_flag[BB * NN];         // node-done flags

__global__ void reset_kernel()
{
    int gt = blockIdx.x * NTHR + threadIdx.x;
    for (int i = gt; i < BB * NN; i += GRID * NTHR) g_flag[i] = 0u;
    for (int i = gt; i < NGRP;   i += GRID * NTHR) g_cnt[i] = 0;
    if (gt < TT) g_tcur[gt] = 0;
    if (gt == 0) { g_arrive = 0; g_release = 0; g_maxl = 0; }
}

__device__ __forceinline__ void grid_barrier(int k)
{
    __syncthreads();
    if (threadIdx.x == 0) {
        __threadfence();   // release side
        unsigned old = atomicAdd(&g_arrive, 1u);
        if (old == (unsigned)(k * GRID - 1)) {
            g_release = (unsigned)k;
        } else {
            while (g_release < (unsigned)k) { }
        }
        __threadfence();   // acquire side
    }
    __syncthreads();
}

// STRONG scoped flag ops — the canonical PTX release/acquire message pair.
__device__ __forceinline__ unsigned ld_acq_u32(const unsigned* p)
{
    unsigned v;
    asm volatile("ld.acquire.gpu.global.u32 %0, [%1];"
                 : "=r"(v) : "l"(p) : "memory");
    return v;
}
__device__ __forceinline__ void st_rel_u32(unsigned* p, unsigned v)
{
    asm volatile("st.release.gpu.global.u32 [%0], %1;"
                 :: "l"(p), "r"(v) : "memory");
}

__global__ __launch_bounds__(NTHR, 3)
void dag_global_kernel(const float* __restrict__ roots,
                       const float* __restrict__ W1,
                       const float* __restrict__ b1,
                       const float* __restrict__ W2,
                       const float* __restrict__ b2,
                       const int*   __restrict__ g_idx,
                       const int*   __restrict__ g_typ,
                       float*       __restrict__ buf)
{
    const int b    = blockIdx.x;
    const int tid  = threadIdx.x;
    const int lane = tid & 31;
    const int wid  = tid >> 5;

    __shared__ __align__(16) float s_xs[KD * MS];
    __shared__ __align__(16) float s_hs[HH * MS];
    __shared__ unsigned long long s_it[2][MCH];  // per-slot chunk items
    __shared__ int s_ccum[LMAX + 1];
    __shared__ int s_k[2], s_goff[2], s_Mc[2];

    unsigned short* s_lvl  = (unsigned short*)s_xs;   // prep aliases
    unsigned short* s_pidx = (unsigned short*)s_hs;

    // ---------------- prep (graphs 0..BB-1 handled by CTAs 0..BB-1) ----------
    if (b < BB) {
        const int* idxb = g_idx + (size_t)b * (NN * 2);
        const float* rs = roots + (size_t)b * (RR * DD);
        float*       bb = buf   + (size_t)b * (NN * DD);
        for (int i = tid; i < RR * DD; i += NTHR) bb[i] = rs[i];
        for (int k = tid; k < NN * 2; k += NTHR)
            s_pidx[k] = (unsigned short)idxb[k];
        for (int n = tid; n < RR; n += NTHR)
            g_flag[b * NN + n] = 1u;
        __syncthreads();

        if (tid == 0) {
            for (int n = 0; n < RR; ++n) s_lvl[n] = 0;
            int mx = 0;
            for (int n = RR; n < NN; ++n) {
                int l0 = s_lvl[s_pidx[n * 2 + 0]];
                int l1 = s_lvl[s_pidx[n * 2 + 1]];
                int l  = 1 + (l0 > l1 ? l0 : l1);
                s_lvl[n] = (unsigned short)l;
                if (l > mx) mx = l;
            }
            atomicMax(&g_maxl, mx);
        }
        __syncthreads();

        const int* typb = g_typ + (size_t)b * NN;
        for (int n = RR + tid; n < NN; n += NTHR)
            atomicAdd(&g_cnt[typb[n] * LMAX + (int)s_lvl[n]], 1);
    }

    grid_barrier(1);

    // CTA0: per-type prefix sums (8 threads, one per type)
    if (b == 0) {
        __shared__ int s_ttot[TT];
        if (tid < TT) {
            int tot = 0;
            for (int L = 0; L < LMAX; ++L) tot += g_cnt[tid * LMAX + L];
            s_ttot[tid] = tot;
        }
        __syncthreads();
        if (tid < TT) {
            int base = 0;
            for (int t = 0; t < tid; ++t) base += s_ttot[t];
            int acc = base;
            for (int L = 0; L < LMAX; ++L) {
                g_off[tid * LMAX + L] = acc;
                g_cur[tid * LMAX + L] = acc;
                acc += g_cnt[tid * LMAX + L];
            }
            if (tid == TT - 1) g_off[NGRP] = acc;
            int cacc = 0;
            g_ccum[tid * (LMAX + 1)] = 0;
            for (int L = 1; L <= LMAX; ++L) {
                cacc += (g_cnt[tid * LMAX + L] + MCH - 1) / MCH;
                g_ccum[tid * (LMAX + 1) + L] = cacc;
            }
        }
    }
    grid_barrier(2);

    // scatter items (64-bit packed with parent indices)
    if (b < BB) {
        const int* typb = g_typ + (size_t)b * NN;
        for (int n = RR + tid; n < NN; n += NTHR) {
            int key = typb[n] * LMAX + (int)s_lvl[n];
            int pos = atomicAdd(&g_cur[key], 1);
            unsigned long long p0 = s_pidx[n * 2 + 0];
            unsigned long long p1 = s_pidx[n * 2 + 1];
            g_items[pos] = ((unsigned long long)b << 33)
                         | ((unsigned long long)n << 22) | (p0 << 11) | p1;
        }
    }
    grid_barrier(3);

    // ---------------- dataflow main loop ----------------
    const int tmy = b % TT;              // teams of 55-56 CTAs
    const int Lmx = *(volatile int*)&g_maxl;

    for (int i = tid; i <= LMAX; i += NTHR) s_ccum[i] = g_ccum[tmy * (LMAX + 1) + i];
    __syncthreads();
    const int total = s_ccum[Lmx];

    const float* w1t = W1 + (size_t)tmy * (KD * HH);
    const float* w2t = W2 + (size_t)tmy * (HH * DD);
    const float  bv1 = __ldg(b1 + tmy * HH + (tid & 127));
    const float  bv2 = __ldg(b2 + tmy * DD + (tid & 63));

    const int j128 = tid & 127, mh = tid >> 7;
    const int d64  = tid & 63,  mq = tid >> 6;

    // ---- startup: claim + blocking poll + gather for slot 0 ----
    if (tid == 0) {
        int k = atomicAdd(&g_tcur[tmy], 1);
        s_k[0] = k;
        if (k < total) {
            int loL = 1, hiL = Lmx;
            while (loL < hiL) { int mid = (loL + hiL) >> 1;
                                if (s_ccum[mid] > k) hiL = mid; else loL = mid + 1; }
            const int L    = loL;
            const int cidx = k - s_ccum[L - 1];
            const int base = g_off[tmy * LMAX + L];
            const int cnt  = g_off[tmy * LMAX + L + 1] - base;
            s_goff[0] = base + cidx * MCH;
            s_Mc[0]   = min(MCH, cnt - cidx * MCH);
        }
    }
    __syncthreads();
    int cur_k = s_k[0], cur_goff = s_goff[0], cur_Mc = s_Mc[0];
    if (cur_k < total) {
        if (tid < cur_Mc) s_it[0][tid] = g_items[cur_goff + tid];
        #pragma unroll
        for (int r = 0; r < 4; ++r) {
            int m = wid + r * 8;
            if (m < cur_Mc) {
                unsigned long long it = g_items[cur_goff + m];
                unsigned gb = (unsigned)(it >> 33);
                unsigned p0 = (unsigned)(it >> 11) & 2047u;
                unsigned p1 = (unsigned)it & 2047u;
                while (ld_acq_u32(&g_flag[gb * NN + p0]) == 0u) { }
                while (ld_acq_u32(&g_flag[gb * NN + p1]) == 0u) { }
                const float* r0 = buf + ((size_t)gb * NN + p0) * DD;
                const float* r1 = buf + ((size_t)gb * NN + p1) * DD;
                s_xs[(lane      ) * MS + m] = __ldcg(r0 + lane);
                s_xs[(lane + 32 ) * MS + m] = __ldcg(r0 + lane + 32);
                s_xs[(lane + 64 ) * MS + m] = __ldcg(r1 + lane);
                s_xs[(lane + 96 ) * MS + m] = __ldcg(r1 + lane + 32);
            }
        }
    }
    int p = 0;

    while (true) {
        if (cur_k >= total) break;
        const int q = p ^ 1;

        // ---- claim next chunk into slot q ----
        if (tid == 0) {
            int k = atomicAdd(&g_tcur[tmy], 1);
            s_k[q] = k;
            if (k < total) {
                int loL = 1, hiL = Lmx;
                while (loL < hiL) { int mid = (loL + hiL) >> 1;
                                    if (s_ccum[mid] > k) hiL = mid; else loL = mid + 1; }
                const int L    = loL;
                const int cidx = k - s_ccum[L - 1];
                const int base = g_off[tmy * LMAX + L];
                const int cnt  = g_off[tmy * LMAX + L + 1] - base;
                s_goff[q] = base + cidx * MCH;
                s_Mc[q]   = min(MCH, cnt - cidx * MCH);
            }
        }
        __syncthreads();   // claim visible; prior s_xs writes ordered before GEMM1
        const int nxt_k    = s_k[q];
        const int nxt_goff = s_goff[q];
        const int nxt_Mc   = s_Mc[q];

        // ---- prefetch TEST for slot q (non-blocking, per-warp verdict) ----
        unsigned long long nit[4];
        bool okw = true;
        if (nxt_k < total) {
            if (tid < nxt_Mc) s_it[q][tid] = g_items[nxt_goff + tid];
            #pragma unroll
            for (int r = 0; r < 4; ++r) {
                int m = wid + r * 8;
                nit[r] = 0;
                if (m < nxt_Mc) {
                    nit[r] = g_items[nxt_goff + m];
                    unsigned gb = (unsigned)(nit[r] >> 33);
                    unsigned p0 = (unsigned)(nit[r] >> 11) & 2047u;
                    unsigned p1 = (unsigned)nit[r] & 2047u;
                    if (ld_acq_u32(&g_flag[gb * NN + p0]) == 0u) okw = false;
                    if (ld_acq_u32(&g_flag[gb * NN + p1]) == 0u) okw = false;
                }
            }
        }

        // ---- GEMM1 + bias + GELU (slot p): pipelined weights + f32x2 FMA ----
        {
            const float* wp = w1t + j128;
            const float* xp = s_xs + mh * 16;
            unsigned long long acc[8];
            #pragma unroll
            for (int z = 0; z < 8; ++z) acc[z] = 0ull;   // (0.0f, 0.0f)
            float wc0 = __ldg(wp + 0 * HH);
            float wc1 = __ldg(wp + 1 * HH);
            float wc2 = __ldg(wp + 2 * HH);
            float wc3 = __ldg(wp + 3 * HH);
            #pragma unroll 1
            for (int i = 0; i < KD; i += 4) {
                const int ip = (i + 4) & (KD - 1);   // wrap: harmless reload of block 0
                float wn0 = __ldg(wp + (ip + 0) * HH);
                float wn1 = __ldg(wp + (ip + 1) * HH);
                float wn2 = __ldg(wp + (ip + 2) * HH);
                float wn3 = __ldg(wp + (ip + 3) * HH);
                #pragma unroll
                for (int u = 0; u < 4; ++u) {
                    float wv = (u == 0) ? wc0 : (u == 1) ? wc1 : (u == 2) ? wc2 : wc3;
                    unsigned long long wv2;
                    PACK_F32X2(wv2, wv, wv);
                    const float* xr = xp + (i + u) * MS;
                    ulonglong2 x01 = *(const ulonglong2*)(xr     );
                    ulonglong2 x23 = *(const ulonglong2*)(xr + 4 );
                    ulonglong2 x45 = *(const ulonglong2*)(xr + 8 );
                    ulonglong2 x67 = *(const ulonglong2*)(xr + 12);
                    FMA_F32X2(acc[0], x01.x, wv2, acc[0]);
                    FMA_F32X2(acc[1], x01.y, wv2, acc[1]);
                    FMA_F32X2(acc[2], x23.x, wv2, acc[2]);
                    FMA_F32X2(acc[3], x23.y, wv2, acc[3]);
                    FMA_F32X2(acc[4], x45.x, wv2, acc[4]);
                    FMA_F32X2(acc[5], x45.y, wv2, acc[5]);
                    FMA_F32X2(acc[6], x67.x, wv2, acc[6]);
                    FMA_F32X2(acc[7], x67.y, wv2, acc[7]);
                }
                wc0 = wn0; wc1 = wn1; wc2 = wn2; wc3 = wn3;
            }
            float a[16];
            #pragma unroll
            for (int z = 0; z < 8; ++z)
                UNPACK_F32X2(a[2 * z], a[2 * z + 1], acc[z]);
            #pragma unroll
            for (int z = 0; z < 16; ++z) {
                float v = a[z] + bv1;
                a[z] = 0.5f * v * (1.0f + erff(v * 0.70710678118654752440f));
            }
            float* hp = s_hs + j128 * MS + mh * 16;
            *(float4*)(hp     ) = make_float4(a[0],  a[1],  a[2],  a[3]);
            *(float4*)(hp + 4 ) = make_float4(a[4],  a[5],  a[6],  a[7]);
            *(float4*)(hp + 8 ) = make_float4(a[8],  a[9],  a[10], a[11]);
            *(float4*)(hp + 12) = make_float4(a[12], a[13], a[14], a[15]);
        }
        __syncthreads();     // s_hs ready; s_xs now DEAD

        // ---- prefetch ISSUE (ok warps): LDG latency rides under GEMM2 ----
        float gx[16];
        const bool do_pref = (nxt_k < total) && okw;
        if (do_pref) {
            #pragma unroll
            for (int r = 0; r < 4; ++r) {
                int m = wid + r * 8;
                if (m < nxt_Mc) {
                    unsigned gb = (unsigned)(nit[r] >> 33);
                    unsigned p0 = (unsigned)(nit[r] >> 11) & 2047u;
                    unsigned p1 = (unsigned)nit[r] & 2047u;
                    const float* r0 = buf + ((size_t)gb * NN + p0) * DD;
                    const float* r1 = buf + ((size_t)gb * NN + p1) * DD;
                    gx[r * 4 + 0] = __ldcg(r0 + lane);
                    gx[r * 4 + 1] = __ldcg(r0 + lane + 32);
                    gx[r * 4 + 2] = __ldcg(r1 + lane);
                    gx[r * 4 + 3] = __ldcg(r1 + lane + 32);
                }
            }
        }

        // ---- GEMM2 + bias + store (slot p): pipelined weights + f32x2 FMA ----
        {
            const float* wp = w2t + d64;
            const float* hp = s_hs + mq * 8;
            unsigned long long acc[4];
            #pragma unroll
            for (int z = 0; z < 4; ++z) acc[z] = 0ull;
            float wc0 = __ldg(wp + 0 * DD);
            float wc1 = __ldg(wp + 1 * DD);
            float wc2 = __ldg(wp + 2 * DD);
            float wc3 = __ldg(wp + 3 * DD);
            #pragma unroll 1
            for (int j = 0; j < HH; j += 4) {
                const int jp = (j + 4) & (HH - 1);
                float wn0 = __ldg(wp + (jp + 0) * DD);
                float wn1 = __ldg(wp + (jp + 1) * DD);
                float wn2 = __ldg(wp + (jp + 2) * DD);
                float wn3 = __ldg(wp + (jp + 3) * DD);
                #pragma unroll
                for (int u = 0; u < 4; ++u) {
                    float wv = (u == 0) ? wc0 : (u == 1) ? wc1 : (u == 2) ? wc2 : wc3;
                    unsigned long long wv2;
                    PACK_F32X2(wv2, wv, wv);
                    const float* hr = hp + (j + u) * MS;
                    ulonglong2 h01 = *(const ulonglong2*)(hr    );
                    ulonglong2 h23 = *(const ulonglong2*)(hr + 4);
                    FMA_F32X2(acc[0], h01.x, wv2, acc[0]);
                    FMA_F32X2(acc[1], h01.y, wv2, acc[1]);
                    FMA_F32X2(acc[2], h23.x, wv2, acc[2]);
                    FMA_F32X2(acc[3], h23.y, wv2, acc[3]);
                }
                wc0 = wn0; wc1 = wn1; wc2 = wn2; wc3 = wn3;
            }
            float o[8];
            #pragma unroll
            for (int z = 0; z < 4; ++z)
                UNPACK_F32X2(o[2 * z], o[2 * z + 1], acc[z]);
            #pragma unroll
            for (int z = 0; z < 8; ++z) {
                int m = mq * 8 + z;
                if (m < cur_Mc) {
                    unsigned long long it = s_it[p][m];          // broadcast LDS
                    unsigned gb = (unsigned)(it >> 33);
                    unsigned gn = (unsigned)(it >> 22) & 2047u;
                    buf[((size_t)gb * NN + gn) * DD + d64] = o[z] + bv2;
                }
            }
        }

        // ---- dump prefetched regs into s_xs (s_xs dead since post-GEMM1 sync) ----
        if (do_pref) {
            #pragma unroll
            for (int r = 0; r < 4; ++r) {
                int m = wid + r * 8;
                if (m < nxt_Mc) {
                    s_xs[(lane      ) * MS + m] = gx[r * 4 + 0];
                    s_xs[(lane + 32 ) * MS + m] = gx[r * 4 + 1];
                    s_xs[(lane + 64 ) * MS + m] = gx[r * 4 + 2];
                    s_xs[(lane + 96 ) * MS + m] = gx[r * 4 + 3];
                }
            }
        }

        // ---- publish slot p: bar (intra-CTA HB) -> release-store (gpu-scope) ----
        __syncthreads();
        if (tid < cur_Mc) {
            unsigned long long it = s_it[p][tid];
            unsigned gb = (unsigned)(it >> 33);
            unsigned gn = (unsigned)(it >> 22) & 2047u;
            st_rel_u32(&g_flag[gb * NN + gn], 1u);
        }

        // ---- failed warps: blocking poll + gather for slot q (after publish) ----
        if (nxt_k < total && !okw) {
            #pragma unroll
            for (int r = 0; r < 4; ++r) {
                int m = wid + r * 8;
                if (m < nxt_Mc) {
                    unsigned gb = (unsigned)(nit[r] >> 33);
                    unsigned p0 = (unsigned)(nit[r] >> 11) & 2047u;
                    unsigned p1 = (unsigned)nit[r] & 2047u;
                    while (ld_acq_u32(&g_flag[gb * NN + p0]) == 0u) { }
                    while (ld_acq_u32(&g_flag[gb * NN + p1]) == 0u) { }
                    const float* r0 = buf + ((size_t)gb * NN + p0) * DD;
                    const float* r1 = buf + ((size_t)gb * NN + p1) * DD;
                    s_xs[(lane      ) * MS + m] = __ldcg(r0 + lane);
                    s_xs[(lane + 32 ) * MS + m] = __ldcg(r0 + lane + 32);
                    s_xs[(lane + 64 ) * MS + m] = __ldcg(r1 + lane);
                    s_xs[(lane + 96 ) * MS + m] = __ldcg(r1 + lane + 32);
                }
            }
        }

        cur_k = nxt_k; cur_goff = nxt_goff; cur_Mc = nxt_Mc;
        p = q;
        // next iteration's post-claim __syncthreads orders all s_xs writes
        // (prefetch dump + blocking path) before GEMM1's reads.
    }
}

extern "C" void kernel_launch(void* const* d_in, const int* in_sizes, int n_in,
                              void* d_out, int out_size)
{
    const float* roots = (const float*)d_in[0];
    const float* W1    = (const float*)d_in[1];
    const float* b1    = (const float*)d_in[2];
    const float* W2    = (const float*)d_in[3];
    const float* b2    = (const float*)d_in[4];
    const int*   idx   = (const int*)  d_in[5];
    const int*   typ   = (const int*)  d_in[6];
    float*       out   = (float*)d_out;

    reset_kernel<<<GRID, NTHR>>>();
    dag_global_kernel<<<GRID, NTHR>>>(roots, W1, b1, W2, b2, idx, typ, out);
}

// round 17
// speedup vs baseline: 1.1985x; 1.0516x over previous
#include <cuda_runtime.h>
#include <math.h>

#define BB 256
#define NN 2048
#define RR 64
#define DD 64
#define TT 8
#define HH 128
#define KD 128

#define GRID    444           // 3 CTAs on every SM (148 x 3), all co-resident
#define NTHR    256
#define MCH     32            // nodes per chunk
#define MS      (MCH + 4)     // smem row stride
#define LMAX    256
#define NGRP    (LMAX * TT)   // bucket key = t*LMAX + L

// packed f32x2 ops (sm_103a double-rate fp32 path; ptxas never auto-emits)
#define FMA_F32X2(d, a, b, c) \
    asm("fma.rn.f32x2 %0, %1, %2, %3;" : "=l"(d) : "l"(a), "l"(b), "l"(c))
#define PACK_F32X2(out, lo, hi) \
    asm("mov.b64 %0, {%1, %2};" : "=l"(out) : "f"(lo), "f"(hi))
#define UNPACK_F32X2(lo, hi, in) \
    asm("mov.b64 {%0, %1}, %2;" : "=f"(lo), "=f"(hi) : "l"(in))

// ---------------- global scratch (static: no allocation) ----------------
__device__ unsigned           g_arrive;
__device__ volatile unsigned  g_release;
__device__ int                g_cnt[NGRP];
__device__ int                g_cur[NGRP];             // scatter cursors
__device__ int                g_off[NGRP + 1];
__device__ int                g_ccum[TT * (LMAX + 1)]; // per-type chunk prefix over levels
__device__ int                g_tcur[TT];              // per-type team chunk cursor
__device__ int                g_maxl;
__device__ unsigned long long g_items[BB * (NN - RR)]; // (b<<33)|(n<<22)|(p0<<11)|p1
__device__ unsigned           g_flag[BB * NN];         // node-done flags

__global__ void reset_kernel()
{
    int gt = blockIdx.x * NTHR + threadIdx.x;
    for (int i = gt; i < BB * NN; i += GRID * NTHR) g_flag[i] = 0u;
    for (int i = gt; i < NGRP;   i += GRID * NTHR) g_cnt[i] = 0;
    if (gt < TT) g_tcur[gt] = 0;
    if (gt == 0) { g_arrive = 0; g_release = 0; g_maxl = 0; }
}

__device__ __forceinline__ void grid_barrier(int k)
{
    __syncthreads();
    if (threadIdx.x == 0) {
        __threadfence();   // release side
        unsigned old = atomicAdd(&g_arrive, 1u);
        if (old == (unsigned)(k * GRID - 1)) {
            g_release = (unsigned)k;
        } else {
            while (g_release < (unsigned)k) { }
        }
        __threadfence();   // acquire side
    }
    __syncthreads();
}

// STRONG scoped flag ops — the canonical PTX release/acquire message pair.
__device__ __forceinline__ unsigned ld_acq_u32(const unsigned* p)
{
    unsigned v;
    asm volatile("ld.acquire.gpu.global.u32 %0, [%1];"
                 : "=r"(v) : "l"(p) : "memory");
    return v;
}
__device__ __forceinline__ void st_rel_u32(unsigned* p, unsigned v)
{
    asm volatile("st.release.gpu.global.u32 [%0], %1;"
                 :: "l"(p), "r"(v) : "memory");
}

__global__ __launch_bounds__(NTHR, 3)
void dag_global_kernel(const float* __restrict__ roots,
                       const float* __restrict__ W1,
                       const float* __restrict__ b1,
                       const float* __restrict__ W2,
                       const float* __restrict__ b2,
                       const int*   __restrict__ g_idx,
                       const int*   __restrict__ g_typ,
                       float*       __restrict__ buf)
{
    const int b    = blockIdx.x;
    const int tid  = threadIdx.x;
    const int lane = tid & 31;
    const int wid  = tid >> 5;

    __shared__ __align__(16) float s_xs[KD * MS];
    __shared__ __align__(16) float s_hs[HH * MS];
    __shared__ unsigned long long s_it[2][MCH];  // per-slot chunk items
    __shared__ int s_ccum[LMAX + 1];
    __shared__ int s_k[2], s_goff[2], s_Mc[2];

    unsigned short* s_lvl  = (unsigned short*)s_xs;   // prep aliases
    unsigned short* s_pidx = (unsigned short*)s_hs;

    // ---------------- prep (graphs 0..BB-1 handled by CTAs 0..BB-1) ----------
    if (b < BB) {
        const int* idxb = g_idx + (size_t)b * (NN * 2);
        const float* rs = roots + (size_t)b * (RR * DD);
        float*       bb = buf   + (size_t)b * (NN * DD);
        for (int i = tid; i < RR * DD; i += NTHR) bb[i] = rs[i];
        for (int k = tid; k < NN * 2; k += NTHR)
            s_pidx[k] = (unsigned short)idxb[k];
        for (int n = tid; n < RR; n += NTHR)
            g_flag[b * NN + n] = 1u;
        __syncthreads();

        if (tid == 0) {
            for (int n = 0; n < RR; ++n) s_lvl[n] = 0;
            int mx = 0;
            for (int n = RR; n < NN; ++n) {
                int l0 = s_lvl[s_pidx[n * 2 + 0]];
                int l1 = s_lvl[s_pidx[n * 2 + 1]];
                int l  = 1 + (l0 > l1 ? l0 : l1);
                s_lvl[n] = (unsigned short)l;
                if (l > mx) mx = l;
            }
            atomicMax(&g_maxl, mx);
        }
        __syncthreads();

        const int* typb = g_typ + (size_t)b * NN;
        for (int n = RR + tid; n < NN; n += NTHR)
            atomicAdd(&g_cnt[typb[n] * LMAX + (int)s_lvl[n]], 1);
    }

    grid_barrier(1);

    // CTA0: per-type prefix sums (8 threads, one per type)
    if (b == 0) {
        __shared__ int s_ttot[TT];
        if (tid < TT) {
            int tot = 0;
            for (int L = 0; L < LMAX; ++L) tot += g_cnt[tid * LMAX + L];
            s_ttot[tid] = tot;
        }
        __syncthreads();
        if (tid < TT) {
            int base = 0;
            for (int t = 0; t < tid; ++t) base += s_ttot[t];
            int acc = base;
            for (int L = 0; L < LMAX; ++L) {
                g_off[tid * LMAX + L] = acc;
                g_cur[tid * LMAX + L] = acc;
                acc += g_cnt[tid * LMAX + L];
            }
            if (tid == TT - 1) g_off[NGRP] = acc;
            int cacc = 0;
            g_ccum[tid * (LMAX + 1)] = 0;
            for (int L = 1; L <= LMAX; ++L) {
                cacc += (g_cnt[tid * LMAX + L] + MCH - 1) / MCH;
                g_ccum[tid * (LMAX + 1) + L] = cacc;
            }
        }
    }
    grid_barrier(2);

    // scatter items (64-bit packed with parent indices)
    if (b < BB) {
        const int* typb = g_typ + (size_t)b * NN;
        for (int n = RR + tid; n < NN; n += NTHR) {
            int key = typb[n] * LMAX + (int)s_lvl[n];
            int pos = atomicAdd(&g_cur[key], 1);
            unsigned long long p0 = s_pidx[n * 2 + 0];
            unsigned long long p1 = s_pidx[n * 2 + 1];
            g_items[pos] = ((unsigned long long)b << 33)
                         | ((unsigned long long)n << 22) | (p0 << 11) | p1;
        }
    }
    grid_barrier(3);

    // ---------------- dataflow main loop ----------------
    const int tmy = b % TT;              // teams of 55-56 CTAs
    const int Lmx = *(volatile int*)&g_maxl;

    for (int i = tid; i <= LMAX; i += NTHR) s_ccum[i] = g_ccum[tmy * (LMAX + 1) + i];
    __syncthreads();
    const int total = s_ccum[Lmx];

    const float* w1t = W1 + (size_t)tmy * (KD * HH);
    const float* w2t = W2 + (size_t)tmy * (HH * DD);

    // GEMM1 mapping: thread = (jpair = tid&63 -> j in {2jp, 2jp+1}, mgroup = tid>>6 -> 8 m)
    const int jp = tid & 63, mg = tid >> 6;
    const float2 bv1 = __ldg((const float2*)(b1 + tmy * HH + 2 * jp));
    // GEMM2 mapping unchanged: (d64, mq of 8 m)
    const int d64 = tid & 63, mq = tid >> 6;
    const float  bv2 = __ldg(b2 + tmy * DD + d64);

    // ---- startup: claim + blocking poll + gather for slot 0 ----
    if (tid == 0) {
        int k = atomicAdd(&g_tcur[tmy], 1);
        s_k[0] = k;
        if (k < total) {
            int loL = 1, hiL = Lmx;
            while (loL < hiL) { int mid = (loL + hiL) >> 1;
                                if (s_ccum[mid] > k) hiL = mid; else loL = mid + 1; }
            const int L    = loL;
            const int cidx = k - s_ccum[L - 1];
            const int base = g_off[tmy * LMAX + L];
            const int cnt  = g_off[tmy * LMAX + L + 1] - base;
            s_goff[0] = base + cidx * MCH;
            s_Mc[0]   = min(MCH, cnt - cidx * MCH);
        }
    }
    __syncthreads();
    int cur_k = s_k[0], cur_goff = s_goff[0], cur_Mc = s_Mc[0];
    if (cur_k < total) {
        if (tid < cur_Mc) s_it[0][tid] = g_items[cur_goff + tid];
        #pragma unroll
        for (int r = 0; r < 4; ++r) {
            int m = wid + r * 8;
            if (m < cur_Mc) {
                unsigned long long it = g_items[cur_goff + m];
                unsigned gb = (unsigned)(it >> 33);
                unsigned p0 = (unsigned)(it >> 11) & 2047u;
                unsigned p1 = (unsigned)it & 2047u;
                while (ld_acq_u32(&g_flag[gb * NN + p0]) == 0u) { }
                while (ld_acq_u32(&g_flag[gb * NN + p1]) == 0u) { }
                const float* r0 = buf + ((size_t)gb * NN + p0) * DD;
                const float* r1 = buf + ((size_t)gb * NN + p1) * DD;
                s_xs[(lane      ) * MS + m] = __ldcg(r0 + lane);
                s_xs[(lane + 32 ) * MS + m] = __ldcg(r0 + lane + 32);
                s_xs[(lane + 64 ) * MS + m] = __ldcg(r1 + lane);
                s_xs[(lane + 96 ) * MS + m] = __ldcg(r1 + lane + 32);
            }
        }
    }
    int p = 0;

    while (true) {
        if (cur_k >= total) break;
        const int q = p ^ 1;

        // ---- claim next chunk into slot q ----
        if (tid == 0) {
            int k = atomicAdd(&g_tcur[tmy], 1);
            s_k[q] = k;
            if (k < total) {
                int loL = 1, hiL = Lmx;
                while (loL < hiL) { int mid = (loL + hiL) >> 1;
                                    if (s_ccum[mid] > k) hiL = mid; else loL = mid + 1; }
                const int L    = loL;
                const int cidx = k - s_ccum[L - 1];
                const int base = g_off[tmy * LMAX + L];
                const int cnt  = g_off[tmy * LMAX + L + 1] - base;
                s_goff[q] = base + cidx * MCH;
                s_Mc[q]   = min(MCH, cnt - cidx * MCH);
            }
        }
        __syncthreads();   // claim visible; prior s_xs writes ordered before GEMM1
        const int nxt_k    = s_k[q];
        const int nxt_goff = s_goff[q];
        const int nxt_Mc   = s_Mc[q];

        // ---- prefetch TEST for slot q (non-blocking, per-warp verdict) ----
        unsigned long long nit[4];
        bool okw = true;
        if (nxt_k < total) {
            if (tid < nxt_Mc) s_it[q][tid] = g_items[nxt_goff + tid];
            #pragma unroll
            for (int r = 0; r < 4; ++r) {
                int m = wid + r * 8;
                nit[r] = 0;
                if (m < nxt_Mc) {
                    nit[r] = g_items[nxt_goff + m];
                    unsigned gb = (unsigned)(nit[r] >> 33);
                    unsigned p0 = (unsigned)(nit[r] >> 11) & 2047u;
                    unsigned p1 = (unsigned)nit[r] & 2047u;
                    if (ld_acq_u32(&g_flag[gb * NN + p0]) == 0u) okw = false;
                    if (ld_acq_u32(&g_flag[gb * NN + p1]) == 0u) okw = false;
                }
            }
        }

        // ---- GEMM1 + bias + GELU (slot p): jpt=2 x mpt=8 mapping ----
        {
            // weights: w1[i][2jp], w1[i][2jp+1] as one float2 LDG.64
            const float2* wp = (const float2*)(w1t) + jp;      // row stride HH/2 float2
            const float*  xp = s_xs + mg * 8;
            unsigned long long acc[8];                          // [j0:4][j1:4]
            #pragma unroll
            for (int z = 0; z < 8; ++z) acc[z] = 0ull;
            float2 wc0 = __ldg(wp + 0 * (HH / 2));
            float2 wc1 = __ldg(wp + 1 * (HH / 2));
            float2 wc2 = __ldg(wp + 2 * (HH / 2));
            float2 wc3 = __ldg(wp + 3 * (HH / 2));
            #pragma unroll 1
            for (int i = 0; i < KD; i += 4) {
                const int ip = (i + 4) & (KD - 1);   // wrap: harmless reload of block 0
                float2 wn0 = __ldg(wp + (ip + 0) * (HH / 2));
                float2 wn1 = __ldg(wp + (ip + 1) * (HH / 2));
                float2 wn2 = __ldg(wp + (ip + 2) * (HH / 2));
                float2 wn3 = __ldg(wp + (ip + 3) * (HH / 2));
                #pragma unroll
                for (int u = 0; u < 4; ++u) {
                    float2 wv = (u == 0) ? wc0 : (u == 1) ? wc1 : (u == 2) ? wc2 : wc3;
                    unsigned long long wva, wvb;
                    PACK_F32X2(wva, wv.x, wv.x);
                    PACK_F32X2(wvb, wv.y, wv.y);
                    const float* xr = xp + (i + u) * MS;
                    ulonglong2 x01 = *(const ulonglong2*)(xr    );
                    ulonglong2 x23 = *(const ulonglong2*)(xr + 4);
                    FMA_F32X2(acc[0], x01.x, wva, acc[0]);
                    FMA_F32X2(acc[1], x01.y, wva, acc[1]);
                    FMA_F32X2(acc[2], x23.x, wva, acc[2]);
                    FMA_F32X2(acc[3], x23.y, wva, acc[3]);
                    FMA_F32X2(acc[4], x01.x, wvb, acc[4]);
                    FMA_F32X2(acc[5], x01.y, wvb, acc[5]);
                    FMA_F32X2(acc[6], x23.x, wvb, acc[6]);
                    FMA_F32X2(acc[7], x23.y, wvb, acc[7]);
                }
                wc0 = wn0; wc1 = wn1; wc2 = wn2; wc3 = wn3;
            }
            float a[16];                                // [j0 m0..7][j1 m0..7]
            #pragma unroll
            for (int z = 0; z < 8; ++z)
                UNPACK_F32X2(a[2 * z], a[2 * z + 1], acc[z]);
            #pragma unroll
            for (int z = 0; z < 8; ++z) {
                float v0 = a[z] + bv1.x;
                a[z] = 0.5f * v0 * (1.0f + erff(v0 * 0.70710678118654752440f));
                float v1 = a[8 + z] + bv1.y;
                a[8 + z] = 0.5f * v1 * (1.0f + erff(v1 * 0.70710678118654752440f));
            }
            float* hp0 = s_hs + (2 * jp    ) * MS + mg * 8;
            float* hp1 = s_hs + (2 * jp + 1) * MS + mg * 8;
            *(float4*)(hp0    ) = make_float4(a[0],  a[1],  a[2],  a[3]);
            *(float4*)(hp0 + 4) = make_float4(a[4],  a[5],  a[6],  a[7]);
            *(float4*)(hp1    ) = make_float4(a[8],  a[9],  a[10], a[11]);
            *(float4*)(hp1 + 4) = make_float4(a[12], a[13], a[14], a[15]);
        }
        __syncthreads();     // s_hs ready; s_xs now DEAD

        // ---- prefetch ISSUE (ok warps): LDG latency rides under GEMM2 ----
        float gx[16];
        const bool do_pref = (nxt_k < total) && okw;
        if (do_pref) {
            #pragma unroll
            for (int r = 0; r < 4; ++r) {
                int m = wid + r * 8;
                if (m < nxt_Mc) {
                    unsigned gb = (unsigned)(nit[r] >> 33);
                    unsigned p0 = (unsigned)(nit[r] >> 11) & 2047u;
                    unsigned p1 = (unsigned)nit[r] & 2047u;
                    const float* r0 = buf + ((size_t)gb * NN + p0) * DD;
                    const float* r1 = buf + ((size_t)gb * NN + p1) * DD;
                    gx[r * 4 + 0] = __ldcg(r0 + lane);
                    gx[r * 4 + 1] = __ldcg(r0 + lane + 32);
                    gx[r * 4 + 2] = __ldcg(r1 + lane);
                    gx[r * 4 + 3] = __ldcg(r1 + lane + 32);
                }
            }
        }

        // ---- GEMM2 + bias + store (slot p): pipelined weights + f32x2 FMA ----
        {
            const float* wp = w2t + d64;
            const float* hp = s_hs + mq * 8;
            unsigned long long acc[4];
            #pragma unroll
            for (int z = 0; z < 4; ++z) acc[z] = 0ull;
            float wc0 = __ldg(wp + 0 * DD);
            float wc1 = __ldg(wp + 1 * DD);
            float wc2 = __ldg(wp + 2 * DD);
            float wc3 = __ldg(wp + 3 * DD);
            #pragma unroll 1
            for (int j = 0; j < HH; j += 4) {
                const int jpn = (j + 4) & (HH - 1);
                float wn0 = __ldg(wp + (jpn + 0) * DD);
                float wn1 = __ldg(wp + (jpn + 1) * DD);
                float wn2 = __ldg(wp + (jpn + 2) * DD);
                float wn3 = __ldg(wp + (jpn + 3) * DD);
                #pragma unroll
                for (int u = 0; u < 4; ++u) {
                    float wv = (u == 0) ? wc0 : (u == 1) ? wc1 : (u == 2) ? wc2 : wc3;
                    unsigned long long wv2;
                    PACK_F32X2(wv2, wv, wv);
                    const float* hr = hp + (j + u) * MS;
                    ulonglong2 h01 = *(const ulonglong2*)(hr    );
                    ulonglong2 h23 = *(const ulonglong2*)(hr + 4);
                    FMA_F32X2(acc[0], h01.x, wv2, acc[0]);
                    FMA_F32X2(acc[1], h01.y, wv2, acc[1]);
                    FMA_F32X2(acc[2], h23.x, wv2, acc[2]);
                    FMA_F32X2(acc[3], h23.y, wv2, acc[3]);
                }
                wc0 = wn0; wc1 = wn1; wc2 = wn2; wc3 = wn3;
            }
            float o[8];
            #pragma unroll
            for (int z = 0; z < 4; ++z)
                UNPACK_F32X2(o[2 * z], o[2 * z + 1], acc[z]);
            #pragma unroll
            for (int z = 0; z < 8; ++z) {
                int m = mq * 8 + z;
                if (m < cur_Mc) {
                    unsigned long long it = s_it[p][m];          // broadcast LDS
                    unsigned gb = (unsigned)(it >> 33);
                    unsigned gn = (unsigned)(it >> 22) & 2047u;
                    buf[((size_t)gb * NN + gn) * DD + d64] = o[z] + bv2;
                }
            }
        }

        // ---- dump prefetched regs into s_xs (s_xs dead since post-GEMM1 sync) ----
        if (do_pref) {
            #pragma unroll
            for (int r = 0; r < 4; ++r) {
                int m = wid + r * 8;
                if (m < nxt_Mc) {
                    s_xs[(lane      ) * MS + m] = gx[r * 4 + 0];
                    s_xs[(lane + 32 ) * MS + m] = gx[r * 4 + 1];
                    s_xs[(lane + 64 ) * MS + m] = gx[r * 4 + 2];
                    s_xs[(lane + 96 ) * MS + m] = gx[r * 4 + 3];
                }
            }
        }

        // ---- publish slot p: bar (intra-CTA HB) -> release-store (gpu-scope) ----
        __syncthreads();
        if (tid < cur_Mc) {
            unsigned long long it = s_it[p][tid];
            unsigned gb = (unsigned)(it >> 33);
            unsigned gn = (unsigned)(it >> 22) & 2047u;
            st_rel_u32(&g_flag[gb * NN + gn], 1u);
        }

        // ---- failed warps: blocking poll + gather for slot q (after publish) ----
        if (nxt_k < total && !okw) {
            #pragma unroll
            for (int r = 0; r < 4; ++r) {
                int m = wid + r * 8;
                if (m < nxt_Mc) {
                    unsigned gb = (unsigned)(nit[r] >> 33);
                    unsigned p0 = (unsigned)(nit[r] >> 11) & 2047u;
                    unsigned p1 = (unsigned)nit[r] & 2047u;
                    while (ld_acq_u32(&g_flag[gb * NN + p0]) == 0u) { }
                    while (ld_acq_u32(&g_flag[gb * NN + p1]) == 0u) { }
                    const float* r0 = buf + ((size_t)gb * NN + p0) * DD;
                    const float* r1 = buf + ((size_t)gb * NN + p1) * DD;
                    s_xs[(lane      ) * MS + m] = __ldcg(r0 + lane);
                    s_xs[(lane + 32 ) * MS + m] = __ldcg(r0 + lane + 32);
                    s_xs[(lane + 64 ) * MS + m] = __ldcg(r1 + lane);
                    s_xs[(lane + 96 ) * MS + m] = __ldcg(r1 + lane + 32);
                }
            }
        }

        cur_k = nxt_k; cur_goff = nxt_goff; cur_Mc = nxt_Mc;
        p = q;
        // next iteration's post-claim __syncthreads orders all s_xs writes
        // (prefetch dump + blocking path) before GEMM1's reads.
    }
}

extern "C" void kernel_launch(void* const* d_in, const int* in_sizes, int n_in,
                              void* d_out, int out_size)
{
    const float* roots = (const float*)d_in[0];
    const float* W1    = (const float*)d_in[1];
    const float* b1    = (const float*)d_in[2];
    const float* W2    = (const float*)d_in[3];
    const float* b2    = (const float*)d_in[4];
    const int*   idx   = (const int*)  d_in[5];
    const int*   typ   = (const int*)  d_in[6];
    float*       out   = (float*)d_out;

    reset_kernel<<<GRID, NTHR>>>();
    dag_global_kernel<<<GRID, NTHR>>>(roots, W1, b1, W2, b2, idx, typ, out);
}